// round 1
// baseline (speedup 1.0000x reference)
#include <cuda_runtime.h>

// DCN cross layer, L=3, D=1024, B=16384.
// One CTA per row. 256 threads x float4 = 1024 floats.
// cross kept in registers; 3 block-level dot products via shfl + smem.

static constexpr int D = 1024;
static constexpr int L = 3;
static constexpr int THREADS = 256;   // 256 * 4 = 1024

__global__ __launch_bounds__(THREADS, 8)
void cross_layer_kernel(const float* __restrict__ x,
                        const float* __restrict__ W,
                        const float* __restrict__ bias,
                        float* __restrict__ out)
{
    const int b = blockIdx.x;
    const int t = threadIdx.x;

    const float4* xrow = reinterpret_cast<const float4*>(x + (size_t)b * D);

    // Front-load everything (MLP): x row chunk + all 3 layers' W/bias chunks.
    float4 xv = xrow[t];
    float4 wv[L], bv[L];
#pragma unroll
    for (int l = 0; l < L; l++) {
        wv[l] = reinterpret_cast<const float4*>(W + l * D)[t];
        bv[l] = reinterpret_cast<const float4*>(bias + l * D)[t];
    }

    float4 cr = xv;

    __shared__ float red[THREADS / 32];

#pragma unroll
    for (int l = 0; l < L; l++) {
        // per-thread partial dot(cross, W_l)
        float p = cr.x * wv[l].x + cr.y * wv[l].y
                + cr.z * wv[l].z + cr.w * wv[l].w;
        // warp reduce
#pragma unroll
        for (int o = 16; o > 0; o >>= 1)
            p += __shfl_xor_sync(0xffffffffu, p, o);

        if (l > 0) __syncthreads();           // protect red[] reuse
        if ((t & 31) == 0) red[t >> 5] = p;
        __syncthreads();

        float s = red[0];
#pragma unroll
        for (int w = 1; w < THREADS / 32; w++) s += red[w];

        // cross = x * s + bias_l + cross
        cr.x = fmaf(xv.x, s, cr.x) + bv[l].x;
        cr.y = fmaf(xv.y, s, cr.y) + bv[l].y;
        cr.z = fmaf(xv.z, s, cr.z) + bv[l].z;
        cr.w = fmaf(xv.w, s, cr.w) + bv[l].w;
    }

    reinterpret_cast<float4*>(out + (size_t)b * D)[t] = cr;
}

extern "C" void kernel_launch(void* const* d_in, const int* in_sizes, int n_in,
                              void* d_out, int out_size)
{
    const float* x    = (const float*)d_in[0];   // (B, D, 1)
    const float* W    = (const float*)d_in[1];   // (L, D, 1)
    const float* bias = (const float*)d_in[2];   // (L, D, 1)
    float* out = (float*)d_out;

    const int B = in_sizes[0] / D;               // 16384
    cross_layer_kernel<<<B, THREADS>>>(x, W, bias, out);
}

// round 2
// speedup vs baseline: 1.0051x; 1.0051x over previous
#include <cuda_runtime.h>

// DCN cross layer, L=3, D=1024, B=16384.
// CTA = 256 threads, thread t owns columns [4t, 4t+4).
// Each CTA processes R=8 rows, so W/bias are loaded from global ONCE per CTA
// and held in registers (kills the 4x L1 amplification seen in R1).
// Per row: 3 block dot-products, one __syncthreads each (3 distinct buffers).

static constexpr int D = 1024;
static constexpr int L = 3;
static constexpr int THREADS = 256;   // 256 * 4 = 1024
static constexpr int R = 8;           // rows per CTA

__global__ __launch_bounds__(THREADS)
void cross_layer_kernel(const float* __restrict__ x,
                        const float* __restrict__ W,
                        const float* __restrict__ bias,
                        float* __restrict__ out)
{
    const int t = threadIdx.x;
    const size_t row0 = (size_t)blockIdx.x * R;

    // W/bias chunks for this thread's 4 columns, all layers: registers, loaded once.
    float4 wv[L], bv[L];
#pragma unroll
    for (int l = 0; l < L; l++) {
        wv[l] = reinterpret_cast<const float4*>(W + l * D)[t];
        bv[l] = reinterpret_cast<const float4*>(bias + l * D)[t];
    }

    __shared__ float red[L][THREADS / 32];

    const float4* xbase = reinterpret_cast<const float4*>(x) + row0 * (D / 4) + t;
    float4* obase = reinterpret_cast<float4*>(out) + row0 * (D / 4) + t;

    // prefetch first row's x (streaming: never reused)
    float4 xv = __ldcs(xbase);

#pragma unroll
    for (int r = 0; r < R; r++) {
        float4 xcur = xv;
        if (r + 1 < R)
            xv = __ldcs(xbase + (size_t)(r + 1) * (D / 4));   // prefetch next row

        float4 cr = xcur;

#pragma unroll
        for (int l = 0; l < L; l++) {
            // partial dot(cross, W_l) over this thread's 4 columns
            float p = cr.x * wv[l].x + cr.y * wv[l].y
                    + cr.z * wv[l].z + cr.w * wv[l].w;
            // warp reduce
#pragma unroll
            for (int o = 16; o > 0; o >>= 1)
                p += __shfl_xor_sync(0xffffffffu, p, o);

            if ((t & 31) == 0) red[l][t >> 5] = p;
            __syncthreads();   // one barrier per layer; buffers distinct per l,
                               // and 2 subsequent barriers separate cross-row reuse

            float s = red[l][0];
#pragma unroll
            for (int w = 1; w < THREADS / 32; w++) s += red[l][w];

            // cross = x * s + bias_l + cross
            cr.x = fmaf(xcur.x, s, cr.x) + bv[l].x;
            cr.y = fmaf(xcur.y, s, cr.y) + bv[l].y;
            cr.z = fmaf(xcur.z, s, cr.z) + bv[l].z;
            cr.w = fmaf(xcur.w, s, cr.w) + bv[l].w;
        }

        __stcs(obase + (size_t)r * (D / 4), cr);   // streaming store
    }
}

extern "C" void kernel_launch(void* const* d_in, const int* in_sizes, int n_in,
                              void* d_out, int out_size)
{
    const float* x    = (const float*)d_in[0];   // (B, D, 1)
    const float* W    = (const float*)d_in[1];   // (L, D, 1)
    const float* bias = (const float*)d_in[2];   // (L, D, 1)
    float* out = (float*)d_out;

    const int B = in_sizes[0] / D;               // 16384
    cross_layer_kernel<<<B / R, THREADS>>>(x, W, bias, out);
}

// round 3
// speedup vs baseline: 1.4823x; 1.4747x over previous
#include <cuda_runtime.h>

// DCN cross layer, L=3, D=1024, B=16384 — algebraic form.
// cross_l = alpha_l * x + sum_{m<l} bias_m, so the whole layer stack reduces to
//   a_l  = dot(x, W_l)           (3 independent dots, one reduction pass)
//   d_ml = dot(bias_m, W_l)      (batch-independent, computed once per CTA)
//   scalar recurrence for alpha, then out = alpha*x + (b0+b1+b2).
// One warp per row: reductions are shfl-only, NO barriers in the row loop.
// x is register-resident (8 float4) load->store. W in smem, conflict-free.

static constexpr int D  = 1024;
static constexpr int F4 = D / 4;          // 256 float4 per row
static constexpr int THREADS = 256;
static constexpr int NWARP = THREADS / 32; // 8 rows per CTA

__device__ __forceinline__ float dot4(float4 a, float4 b) {
    return fmaf(a.x, b.x, fmaf(a.y, b.y, fmaf(a.z, b.z, a.w * b.w)));
}
__device__ __forceinline__ float wred(float v) {
#pragma unroll
    for (int o = 16; o > 0; o >>= 1)
        v += __shfl_xor_sync(0xffffffffu, v, o);
    return v;
}

__global__ __launch_bounds__(THREADS, 4)
void cross_layer_kernel(const float* __restrict__ x,
                        const float* __restrict__ W,
                        const float* __restrict__ bias,
                        float* __restrict__ out)
{
    __shared__ float4 Ws[3][F4];
    __shared__ float4 Bs[F4];            // b0+b1+b2
    __shared__ float  dred[NWARP][3];

    const int t    = threadIdx.x;
    const int warp = t >> 5;
    const int lane = t & 31;

    // ---- prologue: fill smem, compute d01,d02,d12 (once per CTA) ----
    const float4* W4 = reinterpret_cast<const float4*>(W);
    const float4* B4 = reinterpret_cast<const float4*>(bias);
    float4 w1 = W4[F4 + t];
    float4 w2 = W4[2 * F4 + t];
    Ws[0][t] = W4[t];
    Ws[1][t] = w1;
    Ws[2][t] = w2;
    float4 b0 = B4[t], b1 = B4[F4 + t], b2 = B4[2 * F4 + t];
    float4 bs;
    bs.x = b0.x + b1.x + b2.x;  bs.y = b0.y + b1.y + b2.y;
    bs.z = b0.z + b1.z + b2.z;  bs.w = b0.w + b1.w + b2.w;
    Bs[t] = bs;

    float p01 = dot4(b0, w1);
    float p02 = dot4(b0, w2);
    float p12 = dot4(b1, w2);
    p01 = wred(p01); p02 = wred(p02); p12 = wred(p12);
    if (lane == 0) { dred[warp][0] = p01; dred[warp][1] = p02; dred[warp][2] = p12; }
    __syncthreads();

    float d01 = 0.f, d02 = 0.f, d12 = 0.f;
#pragma unroll
    for (int w = 0; w < NWARP; w++) {
        d01 += dred[w][0]; d02 += dred[w][1]; d12 += dred[w][2];
    }
    const float d2 = d02 + d12;

    // ---- one row per warp, no barriers ----
    const size_t row = (size_t)blockIdx.x * NWARP + warp;
    const float4* xr = reinterpret_cast<const float4*>(x) + row * F4;
    float4*       orr = reinterpret_cast<float4*>(out)    + row * F4;

    // load x row: lane owns float4 indices lane + 32j  (coalesced, 8 in flight)
    float4 xv[8];
#pragma unroll
    for (int j = 0; j < 8; j++)
        xv[j] = __ldcs(xr + lane + 32 * j);

    // three independent dots of x against W0,W1,W2 (smem, conflict-free)
    float a0 = 0.f, a1 = 0.f, a2 = 0.f;
#pragma unroll
    for (int j = 0; j < 8; j++) {
        const int idx = lane + 32 * j;
        a0 = fmaf(xv[j].x, Ws[0][idx].x, fmaf(xv[j].y, Ws[0][idx].y,
             fmaf(xv[j].z, Ws[0][idx].z, fmaf(xv[j].w, Ws[0][idx].w, a0))));
        a1 = fmaf(xv[j].x, Ws[1][idx].x, fmaf(xv[j].y, Ws[1][idx].y,
             fmaf(xv[j].z, Ws[1][idx].z, fmaf(xv[j].w, Ws[1][idx].w, a1))));
        a2 = fmaf(xv[j].x, Ws[2][idx].x, fmaf(xv[j].y, Ws[2][idx].y,
             fmaf(xv[j].z, Ws[2][idx].z, fmaf(xv[j].w, Ws[2][idx].w, a2))));
    }
    a0 = wred(a0); a1 = wred(a1); a2 = wred(a2);

    // scalar recurrence
    float al = 1.f + a0;                 // alpha after layer 0
    al += fmaf(al, a1, d01);             // + s1
    al += fmaf(al, a2, d2);              // + s2

    // out = alpha * x + (b0+b1+b2)
#pragma unroll
    for (int j = 0; j < 8; j++) {
        const int idx = lane + 32 * j;
        float4 o, c = Bs[idx];
        o.x = fmaf(al, xv[j].x, c.x);
        o.y = fmaf(al, xv[j].y, c.y);
        o.z = fmaf(al, xv[j].z, c.z);
        o.w = fmaf(al, xv[j].w, c.w);
        __stcs(orr + idx, o);
    }
}

extern "C" void kernel_launch(void* const* d_in, const int* in_sizes, int n_in,
                              void* d_out, int out_size)
{
    const float* x    = (const float*)d_in[0];   // (B, D, 1)
    const float* W    = (const float*)d_in[1];   // (L, D, 1)
    const float* bias = (const float*)d_in[2];   // (L, D, 1)
    float* out = (float*)d_out;

    const int B = in_sizes[0] / D;               // 16384
    cross_layer_kernel<<<B / NWARP, THREADS>>>(x, W, bias, out);
}